// round 2
// baseline (speedup 1.0000x reference)
#include <cuda_runtime.h>
#include <math.h>

#define BATCH 2
#define SEQ   2048
#define DMODEL 1024
#define NQH 16
#define NKH 8
#define HD 128

// -------- scratch (device globals; no allocation allowed) --------
__device__ float g_q[(size_t)BATCH*SEQ*NQH*HD];   // 33.5 MB
__device__ float g_k[(size_t)BATCH*SEQ*NKH*HD];   // 16.8 MB
__device__ float g_v[(size_t)BATCH*SEQ*NKH*HD];   // 16.8 MB
__device__ float g_o[(size_t)BATCH*SEQ*NQH*HD];   // 33.5 MB

// ============================================================
// Generic SGEMM: C[M,N] = A[M,K] @ B[K,N], all row-major fp32.
// 128x128 block tile, BK=16, 256 threads, 8x8 microtile.
// ============================================================
__global__ __launch_bounds__(256) void sgemm_k(
    const float* __restrict__ A, const float* __restrict__ Bm,
    float* __restrict__ C, int M, int N, int K)
{
    __shared__ float sAT[16*136];   // A tile transposed: [k][m], stride 136
    __shared__ float sB [16*132];   // B tile natural:    [k][n], stride 132

    const int tid = threadIdx.x;
    const int tx = tid & 15;
    const int ty = tid >> 4;
    const int m0 = blockIdx.y * 128;
    const int n0 = blockIdx.x * 128;

    float acc[8][8];
    #pragma unroll
    for (int i = 0; i < 8; i++)
        #pragma unroll
        for (int j = 0; j < 8; j++) acc[i][j] = 0.0f;

    for (int kt = 0; kt < K; kt += 16) {
        // --- load A tile (128 x 16) transposed into sAT ---
        #pragma unroll
        for (int it = 0; it < 2; it++) {
            int idx = tid + it * 256;          // 0..511 float4 slots
            int r  = idx >> 2;                 // 0..127
            int c4 = (idx & 3) << 2;           // 0,4,8,12
            float4 a4 = *(const float4*)(A + (size_t)(m0 + r) * K + kt + c4);
            sAT[(c4+0)*136 + r] = a4.x;
            sAT[(c4+1)*136 + r] = a4.y;
            sAT[(c4+2)*136 + r] = a4.z;
            sAT[(c4+3)*136 + r] = a4.w;
        }
        // --- load B tile (16 x 128) natural into sB ---
        #pragma unroll
        for (int it = 0; it < 2; it++) {
            int idx = tid + it * 256;
            int kr = idx >> 5;                 // 0..15
            int c4 = (idx & 31) << 2;          // 0..124
            *(float4*)(sB + kr*132 + c4) =
                *(const float4*)(Bm + (size_t)(kt + kr) * N + n0 + c4);
        }
        __syncthreads();

        #pragma unroll
        for (int k = 0; k < 16; k++) {
            float4 a0 = *(float4*)(sAT + k*136 + 8*ty);
            float4 a1 = *(float4*)(sAT + k*136 + 8*ty + 4);
            float4 b0 = *(float4*)(sB  + k*132 + 8*tx);
            float4 b1 = *(float4*)(sB  + k*132 + 8*tx + 4);
            float av[8] = {a0.x,a0.y,a0.z,a0.w,a1.x,a1.y,a1.z,a1.w};
            float bv[8] = {b0.x,b0.y,b0.z,b0.w,b1.x,b1.y,b1.z,b1.w};
            #pragma unroll
            for (int i = 0; i < 8; i++)
                #pragma unroll
                for (int j = 0; j < 8; j++)
                    acc[i][j] += av[i] * bv[j];
        }
        __syncthreads();
    }

    #pragma unroll
    for (int i = 0; i < 8; i++) {
        float* cp = C + (size_t)(m0 + 8*ty + i) * N + n0 + 8*tx;
        *(float4*)(cp)     = make_float4(acc[i][0],acc[i][1],acc[i][2],acc[i][3]);
        *(float4*)(cp + 4) = make_float4(acc[i][4],acc[i][5],acc[i][6],acc[i][7]);
    }
}

// ============================================================
// Fused RMSNorm (per head vector of 128) + RoPE, in place.
// One block of 128 threads per (b, t, head).
// ============================================================
__global__ __launch_bounds__(128) void norm_rope_k(
    float* __restrict__ x, const float* __restrict__ w,
    const int* __restrict__ pos, int heads)
{
    const int bid = blockIdx.x;
    const int n  = bid % heads;
    const int bt = bid / heads;            // b*SEQ + t
    const int h  = threadIdx.x;
    const size_t base = ((size_t)bt * heads + n) * HD;

    __shared__ float red[4];
    __shared__ float sx[HD];

    float v = x[base + h];
    float ss = v * v;
    #pragma unroll
    for (int off = 16; off >= 1; off >>= 1)
        ss += __shfl_xor_sync(0xffffffffu, ss, off);
    if ((h & 31) == 0) red[h >> 5] = ss;
    __syncthreads();
    float sum = red[0] + red[1] + red[2] + red[3];
    float inv_rms = rsqrtf(sum * (1.0f / HD) + 1e-6f);
    sx[h] = w[h] * v * inv_rms;
    __syncthreads();

    if (h < HD/2) {
        float p  = (float)pos[bt];
        float ts = powf(1000000.0f, ((float)(2 * h)) * (1.0f / HD));
        float ang = p / ts;
        float s, c;
        sincosf(ang, &s, &c);
        float a  = sx[h];
        float b2 = sx[h + HD/2];
        x[base + h]        = a  * c - b2 * s;
        x[base + h + HD/2] = b2 * c + a  * s;
    }
}

// ============================================================
// Causal flash attention (GQA, n_rep=2).
// One block per (q-tile of 64, q head, batch). 256 threads.
// S microtile 4x4 (16x16 thread grid); O microtile 4x8.
// ============================================================
#define SQT_STR 68
#define SV_STR 132
#define SP_STR 68
#define FLASH_SMEM ((128*SQT_STR*2 + 64*SV_STR + 64*SP_STR) * 4)

__global__ __launch_bounds__(256, 1) void flash_k(
    const float* __restrict__ Q, const float* __restrict__ Kk,
    const float* __restrict__ V, float* __restrict__ O)
{
    extern __shared__ float sm[];
    float* sQT = sm;                        // [h=128][r=64] stride 68
    float* sKT = sm + 128*SQT_STR;          // [h=128][c=64] stride 68
    float* sV  = sKT + 128*SQT_STR;         // [s=64][d=128] stride 132
    float* sP  = sV + 64*SV_STR;            // [r=64][s=64]  stride 68

    const int tid = threadIdx.x;
    const int tx = tid & 15;                // key/col group
    const int ty = tid >> 4;                // query/row group
    const int qt = blockIdx.x;
    const int n  = blockIdx.y;
    const int b  = blockIdx.z;
    const int kh = n >> 1;                  // GQA: kv head = n / n_rep
    const int qs = qt * 64;
    const float scale = 0.08838834764831845f;  // 1/sqrt(128)

    // ---- load Q tile transposed (scaled) ----
    for (int idx = tid; idx < 2048; idx += 256) {
        int r  = idx & 63;
        int c4 = (idx >> 6) << 2;
        const float4 q4 = *(const float4*)(
            Q + (((size_t)(b*SEQ + qs + r)) * NQH + n) * HD + c4);
        sQT[(c4+0)*SQT_STR + r] = q4.x * scale;
        sQT[(c4+1)*SQT_STR + r] = q4.y * scale;
        sQT[(c4+2)*SQT_STR + r] = q4.z * scale;
        sQT[(c4+3)*SQT_STR + r] = q4.w * scale;
    }

    float o[4][8];
    #pragma unroll
    for (int i = 0; i < 4; i++)
        #pragma unroll
        for (int j = 0; j < 8; j++) o[i][j] = 0.0f;
    float mrow[4] = {-1e30f, -1e30f, -1e30f, -1e30f};
    float lrow[4] = {0.0f, 0.0f, 0.0f, 0.0f};

    for (int jt = 0; jt <= qt; jt++) {
        const int ks = jt * 64;
        __syncthreads();   // protects sKT/sV/sP consumers of prev iter (and sQT writes at jt=0)

        // ---- load K tile transposed ----
        for (int idx = tid; idx < 2048; idx += 256) {
            int r  = idx & 63;
            int c4 = (idx >> 6) << 2;
            const float4 k4 = *(const float4*)(
                Kk + (((size_t)(b*SEQ + ks + r)) * NKH + kh) * HD + c4);
            sKT[(c4+0)*SQT_STR + r] = k4.x;
            sKT[(c4+1)*SQT_STR + r] = k4.y;
            sKT[(c4+2)*SQT_STR + r] = k4.z;
            sKT[(c4+3)*SQT_STR + r] = k4.w;
        }
        // ---- load V tile natural (coalesced) ----
        for (int idx = tid; idx < 2048; idx += 256) {
            int r  = idx >> 5;
            int c4 = (idx & 31) << 2;
            *(float4*)(sV + r*SV_STR + c4) = *(const float4*)(
                V + (((size_t)(b*SEQ + ks + r)) * NKH + kh) * HD + c4);
        }
        __syncthreads();

        // ---- S = (Q*scale) @ K^T, 4x4 per thread ----
        float s[4][4];
        #pragma unroll
        for (int i = 0; i < 4; i++)
            #pragma unroll
            for (int j = 0; j < 4; j++) s[i][j] = 0.0f;

        #pragma unroll 4
        for (int k = 0; k < HD; k++) {
            float4 q4 = *(float4*)(sQT + k*SQT_STR + 4*ty);
            float4 k4 = *(float4*)(sKT + k*SQT_STR + 4*tx);
            float qv[4] = {q4.x, q4.y, q4.z, q4.w};
            float kv[4] = {k4.x, k4.y, k4.z, k4.w};
            #pragma unroll
            for (int i = 0; i < 4; i++)
                #pragma unroll
                for (int j = 0; j < 4; j++)
                    s[i][j] += qv[i] * kv[j];
        }

        // ---- causal mask on diagonal tile ----
        if (jt == qt) {
            #pragma unroll
            for (int i = 0; i < 4; i++)
                #pragma unroll
                for (int j = 0; j < 4; j++)
                    if (ks + 4*tx + j > qs + 4*ty + i) s[i][j] = -1e30f;
        }

        // ---- online softmax update ----
        #pragma unroll
        for (int i = 0; i < 4; i++) {
            float mx = fmaxf(fmaxf(s[i][0], s[i][1]), fmaxf(s[i][2], s[i][3]));
            #pragma unroll
            for (int off = 8; off >= 1; off >>= 1)
                mx = fmaxf(mx, __shfl_xor_sync(0xffffffffu, mx, off));
            float mnew = fmaxf(mrow[i], mx);
            float cf = expf(mrow[i] - mnew);
            float rs = 0.0f;
            #pragma unroll
            for (int j = 0; j < 4; j++) {
                s[i][j] = expf(s[i][j] - mnew);
                rs += s[i][j];
            }
            #pragma unroll
            for (int off = 8; off >= 1; off >>= 1)
                rs += __shfl_xor_sync(0xffffffffu, rs, off);
            lrow[i] = lrow[i] * cf + rs;
            mrow[i] = mnew;
            #pragma unroll
            for (int j = 0; j < 8; j++) o[i][j] *= cf;
            *(float4*)(sP + (4*ty + i)*SP_STR + 4*tx) =
                make_float4(s[i][0], s[i][1], s[i][2], s[i][3]);
        }
        __syncthreads();

        // ---- O += P @ V, 4x8 per thread ----
        #pragma unroll 2
        for (int s2 = 0; s2 < 64; s2++) {
            float4 v0 = *(float4*)(sV + s2*SV_STR + 8*tx);
            float4 v1 = *(float4*)(sV + s2*SV_STR + 8*tx + 4);
            float vv[8] = {v0.x,v0.y,v0.z,v0.w,v1.x,v1.y,v1.z,v1.w};
            #pragma unroll
            for (int i = 0; i < 4; i++) {
                float p = sP[(4*ty + i)*SP_STR + s2];
                #pragma unroll
                for (int j = 0; j < 8; j++)
                    o[i][j] += p * vv[j];
            }
        }
    }

    // ---- epilogue: normalize and write ----
    #pragma unroll
    for (int i = 0; i < 4; i++) {
        float inv = 1.0f / lrow[i];
        float* op = O + (((size_t)(b*SEQ + qs + 4*ty + i)) * NQH + n) * HD + 8*tx;
        *(float4*)(op)     = make_float4(o[i][0]*inv, o[i][1]*inv, o[i][2]*inv, o[i][3]*inv);
        *(float4*)(op + 4) = make_float4(o[i][4]*inv, o[i][5]*inv, o[i][6]*inv, o[i][7]*inv);
    }
}

// ============================================================
// Host launcher
// ============================================================
extern "C" void kernel_launch(void* const* d_in, const int* in_sizes, int n_in,
                              void* d_out, int out_size)
{
    const float* x      = (const float*)d_in[0];
    const int*   segpos = (const int*)  d_in[1];
    // d_in[2] = attn_mask (bool causal tril) — implied by causal loop, unused
    const float* wq     = (const float*)d_in[3];
    const float* wk     = (const float*)d_in[4];
    const float* wv     = (const float*)d_in[5];
    const float* wo     = (const float*)d_in[6];
    const float* qnw    = (const float*)d_in[7];
    const float* knw    = (const float*)d_in[8];
    float* out = (float*)d_out;

    float *gq, *gk, *gv, *go;
    cudaGetSymbolAddress((void**)&gq, g_q);
    cudaGetSymbolAddress((void**)&gk, g_k);
    cudaGetSymbolAddress((void**)&gv, g_v);
    cudaGetSymbolAddress((void**)&go, g_o);

    cudaFuncSetAttribute(flash_k, cudaFuncAttributeMaxDynamicSharedMemorySize,
                         FLASH_SMEM);

    const int M = BATCH * SEQ;   // 4096

    // QKV projections
    sgemm_k<<<dim3((NQH*HD)/128, M/128), 256>>>(x, wq, gq, M, NQH*HD, DMODEL);
    sgemm_k<<<dim3((NKH*HD)/128, M/128), 256>>>(x, wk, gk, M, NKH*HD, DMODEL);
    sgemm_k<<<dim3((NKH*HD)/128, M/128), 256>>>(x, wv, gv, M, NKH*HD, DMODEL);

    // RMSNorm + RoPE on q and k
    norm_rope_k<<<M * NQH, 128>>>(gq, qnw, segpos, NQH);
    norm_rope_k<<<M * NKH, 128>>>(gk, knw, segpos, NKH);

    // Causal GQA flash attention
    flash_k<<<dim3(SEQ/64, NQH, BATCH), 256, FLASH_SMEM>>>(gq, gk, gv, go);

    // Output projection
    sgemm_k<<<dim3(DMODEL/128, M/128), 256>>>(go, wo, out, M, DMODEL, NQH*HD);
}

// round 3
// speedup vs baseline: 1.0004x; 1.0004x over previous
#include <cuda_runtime.h>
#include <math.h>

#define BATCH 2
#define SEQ   2048
#define DMODEL 1024
#define NQH 16
#define NKH 8
#define HD 128

// -------- scratch (device globals; no allocation allowed) --------
__device__ float g_q[(size_t)BATCH*SEQ*NQH*HD];   // 33.5 MB
__device__ float g_k[(size_t)BATCH*SEQ*NKH*HD];   // 16.8 MB
__device__ float g_v[(size_t)BATCH*SEQ*NKH*HD];   // 16.8 MB
__device__ float g_o[(size_t)BATCH*SEQ*NQH*HD];   // 33.5 MB

// ============================================================
// Generic SGEMM: C[M,N] = A[M,K] @ B[K,N], all row-major fp32.
// 128x128 block tile, BK=16, 256 threads, 8x8 microtile.
// ============================================================
__global__ __launch_bounds__(256) void sgemm_k(
    const float* __restrict__ A, const float* __restrict__ Bm,
    float* __restrict__ C, int M, int N, int K)
{
    __shared__ float sAT[16*136];   // A tile transposed: [k][m], stride 136
    __shared__ float sB [16*132];   // B tile natural:    [k][n], stride 132

    const int tid = threadIdx.x;
    const int tx = tid & 15;
    const int ty = tid >> 4;
    const int m0 = blockIdx.y * 128;
    const int n0 = blockIdx.x * 128;

    float acc[8][8];
    #pragma unroll
    for (int i = 0; i < 8; i++)
        #pragma unroll
        for (int j = 0; j < 8; j++) acc[i][j] = 0.0f;

    for (int kt = 0; kt < K; kt += 16) {
        // --- load A tile (128 x 16) transposed into sAT ---
        #pragma unroll
        for (int it = 0; it < 2; it++) {
            int idx = tid + it * 256;          // 0..511 float4 slots
            int r  = idx >> 2;                 // 0..127
            int c4 = (idx & 3) << 2;           // 0,4,8,12
            float4 a4 = *(const float4*)(A + (size_t)(m0 + r) * K + kt + c4);
            sAT[(c4+0)*136 + r] = a4.x;
            sAT[(c4+1)*136 + r] = a4.y;
            sAT[(c4+2)*136 + r] = a4.z;
            sAT[(c4+3)*136 + r] = a4.w;
        }
        // --- load B tile (16 x 128) natural into sB ---
        #pragma unroll
        for (int it = 0; it < 2; it++) {
            int idx = tid + it * 256;
            int kr = idx >> 5;                 // 0..15
            int c4 = (idx & 31) << 2;          // 0..124
            *(float4*)(sB + kr*132 + c4) =
                *(const float4*)(Bm + (size_t)(kt + kr) * N + n0 + c4);
        }
        __syncthreads();

        #pragma unroll
        for (int k = 0; k < 16; k++) {
            float4 a0 = *(float4*)(sAT + k*136 + 8*ty);
            float4 a1 = *(float4*)(sAT + k*136 + 8*ty + 4);
            float4 b0 = *(float4*)(sB  + k*132 + 8*tx);
            float4 b1 = *(float4*)(sB  + k*132 + 8*tx + 4);
            float av[8] = {a0.x,a0.y,a0.z,a0.w,a1.x,a1.y,a1.z,a1.w};
            float bv[8] = {b0.x,b0.y,b0.z,b0.w,b1.x,b1.y,b1.z,b1.w};
            #pragma unroll
            for (int i = 0; i < 8; i++)
                #pragma unroll
                for (int j = 0; j < 8; j++)
                    acc[i][j] += av[i] * bv[j];
        }
        __syncthreads();
    }

    #pragma unroll
    for (int i = 0; i < 8; i++) {
        float* cp = C + (size_t)(m0 + 8*ty + i) * N + n0 + 8*tx;
        *(float4*)(cp)     = make_float4(acc[i][0],acc[i][1],acc[i][2],acc[i][3]);
        *(float4*)(cp + 4) = make_float4(acc[i][4],acc[i][5],acc[i][6],acc[i][7]);
    }
}

// ============================================================
// Fused RMSNorm (per head vector of 128) + RoPE, in place.
// One block of 128 threads per (b, t, head).
// ============================================================
__global__ __launch_bounds__(128) void norm_rope_k(
    float* __restrict__ x, const float* __restrict__ w,
    const int* __restrict__ pos, int heads)
{
    const int bid = blockIdx.x;
    const int n  = bid % heads;
    const int bt = bid / heads;            // b*SEQ + t
    const int h  = threadIdx.x;
    const size_t base = ((size_t)bt * heads + n) * HD;

    __shared__ float red[4];
    __shared__ float sx[HD];

    float v = x[base + h];
    float ss = v * v;
    #pragma unroll
    for (int off = 16; off >= 1; off >>= 1)
        ss += __shfl_xor_sync(0xffffffffu, ss, off);
    if ((h & 31) == 0) red[h >> 5] = ss;
    __syncthreads();
    float sum = red[0] + red[1] + red[2] + red[3];
    float inv_rms = rsqrtf(sum * (1.0f / HD) + 1e-6f);
    sx[h] = w[h] * v * inv_rms;
    __syncthreads();

    if (h < HD/2) {
        float p  = (float)pos[bt];
        float ts = powf(1000000.0f, ((float)(2 * h)) * (1.0f / HD));
        float ang = p / ts;
        float s, c;
        sincosf(ang, &s, &c);
        float a  = sx[h];
        float b2 = sx[h + HD/2];
        x[base + h]        = a  * c - b2 * s;
        x[base + h + HD/2] = b2 * c + a  * s;
    }
}

// ============================================================
// Causal flash attention (GQA, n_rep=2).
// One block per (q-tile of 64, q head, batch). 256 threads.
// S microtile 4x4 (16x16 thread grid); O microtile 4x8.
// ============================================================
#define SQT_STR 68
#define SV_STR 132
#define SP_STR 68
#define FLASH_SMEM ((128*SQT_STR*2 + 64*SV_STR + 64*SP_STR) * 4)

__global__ __launch_bounds__(256, 1) void flash_k(
    const float* __restrict__ Q, const float* __restrict__ Kk,
    const float* __restrict__ V, float* __restrict__ O)
{
    extern __shared__ float sm[];
    float* sQT = sm;                        // [h=128][r=64] stride 68
    float* sKT = sm + 128*SQT_STR;          // [h=128][c=64] stride 68
    float* sV  = sKT + 128*SQT_STR;         // [s=64][d=128] stride 132
    float* sP  = sV + 64*SV_STR;            // [r=64][s=64]  stride 68

    const int tid = threadIdx.x;
    const int tx = tid & 15;                // key/col group
    const int ty = tid >> 4;                // query/row group
    const int qt = blockIdx.x;
    const int n  = blockIdx.y;
    const int b  = blockIdx.z;
    const int kh = n >> 1;                  // GQA: kv head = n / n_rep
    const int qs = qt * 64;
    const float scale = 0.08838834764831845f;  // 1/sqrt(128)

    // ---- load Q tile transposed (scaled) ----
    for (int idx = tid; idx < 2048; idx += 256) {
        int r  = idx & 63;
        int c4 = (idx >> 6) << 2;
        const float4 q4 = *(const float4*)(
            Q + (((size_t)(b*SEQ + qs + r)) * NQH + n) * HD + c4);
        sQT[(c4+0)*SQT_STR + r] = q4.x * scale;
        sQT[(c4+1)*SQT_STR + r] = q4.y * scale;
        sQT[(c4+2)*SQT_STR + r] = q4.z * scale;
        sQT[(c4+3)*SQT_STR + r] = q4.w * scale;
    }

    float o[4][8];
    #pragma unroll
    for (int i = 0; i < 4; i++)
        #pragma unroll
        for (int j = 0; j < 8; j++) o[i][j] = 0.0f;
    float mrow[4] = {-1e30f, -1e30f, -1e30f, -1e30f};
    float lrow[4] = {0.0f, 0.0f, 0.0f, 0.0f};

    for (int jt = 0; jt <= qt; jt++) {
        const int ks = jt * 64;
        __syncthreads();   // protects sKT/sV/sP consumers of prev iter (and sQT writes at jt=0)

        // ---- load K tile transposed ----
        for (int idx = tid; idx < 2048; idx += 256) {
            int r  = idx & 63;
            int c4 = (idx >> 6) << 2;
            const float4 k4 = *(const float4*)(
                Kk + (((size_t)(b*SEQ + ks + r)) * NKH + kh) * HD + c4);
            sKT[(c4+0)*SQT_STR + r] = k4.x;
            sKT[(c4+1)*SQT_STR + r] = k4.y;
            sKT[(c4+2)*SQT_STR + r] = k4.z;
            sKT[(c4+3)*SQT_STR + r] = k4.w;
        }
        // ---- load V tile natural (coalesced) ----
        for (int idx = tid; idx < 2048; idx += 256) {
            int r  = idx >> 5;
            int c4 = (idx & 31) << 2;
            *(float4*)(sV + r*SV_STR + c4) = *(const float4*)(
                V + (((size_t)(b*SEQ + ks + r)) * NKH + kh) * HD + c4);
        }
        __syncthreads();

        // ---- S = (Q*scale) @ K^T, 4x4 per thread ----
        float s[4][4];
        #pragma unroll
        for (int i = 0; i < 4; i++)
            #pragma unroll
            for (int j = 0; j < 4; j++) s[i][j] = 0.0f;

        #pragma unroll 4
        for (int k = 0; k < HD; k++) {
            float4 q4 = *(float4*)(sQT + k*SQT_STR + 4*ty);
            float4 k4 = *(float4*)(sKT + k*SQT_STR + 4*tx);
            float qv[4] = {q4.x, q4.y, q4.z, q4.w};
            float kv[4] = {k4.x, k4.y, k4.z, k4.w};
            #pragma unroll
            for (int i = 0; i < 4; i++)
                #pragma unroll
                for (int j = 0; j < 4; j++)
                    s[i][j] += qv[i] * kv[j];
        }

        // ---- causal mask on diagonal tile ----
        if (jt == qt) {
            #pragma unroll
            for (int i = 0; i < 4; i++)
                #pragma unroll
                for (int j = 0; j < 4; j++)
                    if (ks + 4*tx + j > qs + 4*ty + i) s[i][j] = -1e30f;
        }

        // ---- online softmax update ----
        #pragma unroll
        for (int i = 0; i < 4; i++) {
            float mx = fmaxf(fmaxf(s[i][0], s[i][1]), fmaxf(s[i][2], s[i][3]));
            #pragma unroll
            for (int off = 8; off >= 1; off >>= 1)
                mx = fmaxf(mx, __shfl_xor_sync(0xffffffffu, mx, off));
            float mnew = fmaxf(mrow[i], mx);
            float cf = expf(mrow[i] - mnew);
            float rs = 0.0f;
            #pragma unroll
            for (int j = 0; j < 4; j++) {
                s[i][j] = expf(s[i][j] - mnew);
                rs += s[i][j];
            }
            #pragma unroll
            for (int off = 8; off >= 1; off >>= 1)
                rs += __shfl_xor_sync(0xffffffffu, rs, off);
            lrow[i] = lrow[i] * cf + rs;
            mrow[i] = mnew;
            #pragma unroll
            for (int j = 0; j < 8; j++) o[i][j] *= cf;
            *(float4*)(sP + (4*ty + i)*SP_STR + 4*tx) =
                make_float4(s[i][0], s[i][1], s[i][2], s[i][3]);
        }
        __syncthreads();

        // ---- O += P @ V, 4x8 per thread ----
        #pragma unroll 2
        for (int s2 = 0; s2 < 64; s2++) {
            float4 v0 = *(float4*)(sV + s2*SV_STR + 8*tx);
            float4 v1 = *(float4*)(sV + s2*SV_STR + 8*tx + 4);
            float vv[8] = {v0.x,v0.y,v0.z,v0.w,v1.x,v1.y,v1.z,v1.w};
            #pragma unroll
            for (int i = 0; i < 4; i++) {
                float p = sP[(4*ty + i)*SP_STR + s2];
                #pragma unroll
                for (int j = 0; j < 8; j++)
                    o[i][j] += p * vv[j];
            }
        }
    }

    // ---- epilogue: normalize and write ----
    #pragma unroll
    for (int i = 0; i < 4; i++) {
        float inv = 1.0f / lrow[i];
        float* op = O + (((size_t)(b*SEQ + qs + 4*ty + i)) * NQH + n) * HD + 8*tx;
        *(float4*)(op)     = make_float4(o[i][0]*inv, o[i][1]*inv, o[i][2]*inv, o[i][3]*inv);
        *(float4*)(op + 4) = make_float4(o[i][4]*inv, o[i][5]*inv, o[i][6]*inv, o[i][7]*inv);
    }
}

// ============================================================
// Host launcher
// ============================================================
extern "C" void kernel_launch(void* const* d_in, const int* in_sizes, int n_in,
                              void* d_out, int out_size)
{
    const float* x      = (const float*)d_in[0];
    const int*   segpos = (const int*)  d_in[1];
    // d_in[2] = attn_mask (bool causal tril) — implied by causal loop, unused
    const float* wq     = (const float*)d_in[3];
    const float* wk     = (const float*)d_in[4];
    const float* wv     = (const float*)d_in[5];
    const float* wo     = (const float*)d_in[6];
    const float* qnw    = (const float*)d_in[7];
    const float* knw    = (const float*)d_in[8];
    float* out = (float*)d_out;

    float *gq, *gk, *gv, *go;
    cudaGetSymbolAddress((void**)&gq, g_q);
    cudaGetSymbolAddress((void**)&gk, g_k);
    cudaGetSymbolAddress((void**)&gv, g_v);
    cudaGetSymbolAddress((void**)&go, g_o);

    cudaFuncSetAttribute(flash_k, cudaFuncAttributeMaxDynamicSharedMemorySize,
                         FLASH_SMEM);

    const int M = BATCH * SEQ;   // 4096

    // QKV projections
    sgemm_k<<<dim3((NQH*HD)/128, M/128), 256>>>(x, wq, gq, M, NQH*HD, DMODEL);
    sgemm_k<<<dim3((NKH*HD)/128, M/128), 256>>>(x, wk, gk, M, NKH*HD, DMODEL);
    sgemm_k<<<dim3((NKH*HD)/128, M/128), 256>>>(x, wv, gv, M, NKH*HD, DMODEL);

    // RMSNorm + RoPE on q and k
    norm_rope_k<<<M * NQH, 128>>>(gq, qnw, segpos, NQH);
    norm_rope_k<<<M * NKH, 128>>>(gk, knw, segpos, NKH);

    // Causal GQA flash attention
    flash_k<<<dim3(SEQ/64, NQH, BATCH), 256, FLASH_SMEM>>>(gq, gk, gv, go);

    // Output projection
    sgemm_k<<<dim3(DMODEL/128, M/128), 256>>>(go, wo, out, M, DMODEL, NQH*HD);
}